// round 5
// baseline (speedup 1.0000x reference)
#include <cuda_runtime.h>
#include <cuda_fp16.h>
#include <cstdint>

#define N_NODES 100000
#define N_EDGES 2000000
#define DIM     64
#define F_IN    128
#define R_REL   64
#define ER_REL  2048
#define RF_REL  64
#define NCLS    16

// ---------------- scratch (static device memory; no allocations) ----------------
__device__ __align__(16) float g_x0[N_NODES * DIM];        // x2 output of conv2 (fp32)
__device__ __align__(16) __half2 g_x0h[N_NODES * DIM / 2]; // fp16 mirror of x0 (proj output)
__device__ __align__(16) __half2 g_x1h[N_NODES * DIM / 2]; // fp16 mirror of x1 (conv1 output)
__device__ __align__(16) float g_wrel[R_REL * DIM];        // per-relation edge weight table
__device__ int g_cnt[N_NODES];            // degree counts
__device__ int g_cur[N_NODES];            // fill cursors
__device__ int g_rowptr[N_NODES + 1];     // CSR row pointers (by dst)
__device__ unsigned g_eadj[N_EDGES];      // packed (src<<6 | etype), sorted by dst

// ---------------- helpers ----------------
__device__ __forceinline__ void red_add_s32(int* addr, int v) {
    asm volatile("red.global.add.s32 [%0], %1;" :: "l"(addr), "r"(v) : "memory");
}

// ---------------- CSR build ----------------
__global__ void zero_cnt_kernel() {
    int i = blockIdx.x * blockDim.x + threadIdx.x;
    if (i < N_NODES) g_cnt[i] = 0;
}

__global__ void count_kernel(const int* __restrict__ dst) {
    int e = blockIdx.x * blockDim.x + threadIdx.x;
    if (e < N_EDGES) red_add_s32(&g_cnt[dst[e]], 1);
}

// Exclusive prefix sum over 100k counts. One block, 1024 threads, chunk=98.
__global__ void scan_kernel() {
    __shared__ int ps[1024];
    int tid = threadIdx.x;
    const int CHUNK = 98;  // 1024*98 = 100352 >= 100000
    int lo = tid * CHUNK;
    int hi = min(lo + CHUNK, N_NODES);
    int sum = 0;
    for (int i = lo; i < hi; ++i) sum += g_cnt[i];
    ps[tid] = sum;
    __syncthreads();
    #pragma unroll
    for (int off = 1; off < 1024; off <<= 1) {
        int v = (tid >= off) ? ps[tid - off] : 0;
        __syncthreads();
        ps[tid] += v;
        __syncthreads();
    }
    int running = ps[tid] - sum;  // exclusive prefix of this chunk
    for (int i = lo; i < hi; ++i) {
        g_rowptr[i] = running;
        g_cur[i]    = running;
        running += g_cnt[i];
    }
    if (tid == 1023) g_rowptr[N_NODES] = ps[1023];
}

__global__ void fill_kernel(const int* __restrict__ ei,
                            const int* __restrict__ et) {
    int e = blockIdx.x * blockDim.x + threadIdx.x;
    if (e >= N_EDGES) return;
    int s = __ldg(ei + e);
    int d = __ldg(ei + N_EDGES + e);
    int r = __ldg(et + e);
    int pos = atomicAdd(&g_cur[d], 1);
    g_eadj[pos] = ((unsigned)s << 6) | (unsigned)r;
}

// ---------------- relation conv + edge-weight table ----------------
__global__ void rel_kernel(const float* __restrict__ rel_x,
                           const int*   __restrict__ rel_ei,
                           const float* __restrict__ rel_ea,
                           const float* __restrict__ W_nn,
                           const float* __restrict__ b_nn) {
    __shared__ __align__(16) float h[R_REL * RF_REL];   // 16 KB
    __shared__ __align__(16) float A[R_REL * R_REL];    // 16 KB (reused for W_nn)
    __shared__ float cnt[R_REL];
    int tid = threadIdx.x;  // 1024

    for (int i = tid; i < R_REL * RF_REL; i += 1024) { h[i] = rel_x[i]; A[i] = 0.f; }
    if (tid < R_REL) cnt[tid] = 0.f;
    __syncthreads();

    for (int e = tid; e < ER_REL; e += 1024) {
        int sr = rel_ei[e];
        int dr = rel_ei[ER_REL + e];
        float a = rel_ea[e];
        atomicAdd(&A[dr * R_REL + sr], a);
        atomicAdd(&cnt[dr], 1.0f);
    }
    __syncthreads();

    int r  = tid >> 4;          // 64 rows, 16 threads per row
    int c4 = (tid & 15) * 4;
    float inv = 1.0f / fmaxf(cnt[r], 1.0f);

    #pragma unroll
    for (int it = 0; it < 2; ++it) {
        float4 acc = make_float4(0.f, 0.f, 0.f, 0.f);
        #pragma unroll 8
        for (int k = 0; k < R_REL; ++k) {
            float a = A[r * R_REL + k];
            float4 hv = *(const float4*)&h[k * RF_REL + c4];
            acc.x += a * hv.x; acc.y += a * hv.y;
            acc.z += a * hv.z; acc.w += a * hv.w;
        }
        __syncthreads();
        float4 hv = *(const float4*)&h[r * RF_REL + c4];
        hv.x = fmaxf(hv.x + acc.x * inv, 0.f);
        hv.y = fmaxf(hv.y + acc.y * inv, 0.f);
        hv.z = fmaxf(hv.z + acc.z * inv, 0.f);
        hv.w = fmaxf(hv.w + acc.w * inv, 0.f);
        *(float4*)&h[r * RF_REL + c4] = hv;
        __syncthreads();
    }

    for (int i = tid; i < RF_REL * DIM; i += 1024) A[i] = W_nn[i];
    __syncthreads();
    float4 acc = make_float4(b_nn[c4], b_nn[c4 + 1], b_nn[c4 + 2], b_nn[c4 + 3]);
    #pragma unroll 8
    for (int k = 0; k < RF_REL; ++k) {
        float hv = h[r * RF_REL + k];
        float4 wv = *(const float4*)&A[k * DIM + c4];
        acc.x += hv * wv.x; acc.y += hv * wv.y;
        acc.z += hv * wv.z; acc.w += hv * wv.w;
    }
    *(float4*)&g_wrel[r * DIM + c4] = acc;
}

// x0 = x_in @ fc1 -> fp16 mirror only. 128-node tiles, 4 nodes x 8 cols per thread.
__global__ void proj_kernel(const float* __restrict__ x_in,
                            const float* __restrict__ fc1) {
    __shared__ __align__(16) float fs[F_IN * DIM];   // 32 KB
    __shared__ __align__(16) float is[128 * 32];     // 16 KB, swizzled
    int tid = threadIdx.x;  // 256
    for (int i = tid; i < F_IN * DIM; i += 256) fs[i] = fc1[i];

    int c8 = (tid & 7) * 8;      // 8 output cols
    int n4 = (tid >> 3) * 4;     // 4 nodes (0..124)
    int sw = tid >> 3;           // == row>>2 for rows n4..n4+3
    int base = blockIdx.x * 128;

    float acc[4][8];
    #pragma unroll
    for (int j = 0; j < 4; ++j)
        #pragma unroll
        for (int i = 0; i < 8; ++i) acc[j][i] = 0.f;

    #pragma unroll
    for (int kb = 0; kb < F_IN; kb += 32) {
        __syncthreads();
        for (int i = tid; i < 128 * 32; i += 256) {
            int nn = i >> 5, k = i & 31;
            int n = base + nn;
            is[nn * 32 + (k ^ ((nn >> 2) & 31))] =
                (n < N_NODES) ? x_in[(size_t)n * F_IN + kb + k] : 0.f;
        }
        __syncthreads();
        #pragma unroll 4
        for (int kk = 0; kk < 32; ++kk) {
            float4 f0 = *(const float4*)&fs[(kb + kk) * DIM + c8];
            float4 f1 = *(const float4*)&fs[(kb + kk) * DIM + c8 + 4];
            int ks = kk ^ (sw & 31);
            #pragma unroll
            for (int j = 0; j < 4; ++j) {
                float iv = is[(n4 + j) * 32 + ks];
                acc[j][0] += iv * f0.x; acc[j][1] += iv * f0.y;
                acc[j][2] += iv * f0.z; acc[j][3] += iv * f0.w;
                acc[j][4] += iv * f1.x; acc[j][5] += iv * f1.y;
                acc[j][6] += iv * f1.z; acc[j][7] += iv * f1.w;
            }
        }
    }
    #pragma unroll
    for (int j = 0; j < 4; ++j) {
        int n = base + n4 + j;
        if (n < N_NODES) {
            __half2 h0 = __floats2half2_rn(acc[j][0], acc[j][1]);
            __half2 h1 = __floats2half2_rn(acc[j][2], acc[j][3]);
            __half2 h2 = __floats2half2_rn(acc[j][4], acc[j][5]);
            __half2 h3 = __floats2half2_rn(acc[j][6], acc[j][7]);
            uint4 p = make_uint4(*(uint32_t*)&h0, *(uint32_t*)&h1,
                                 *(uint32_t*)&h2, *(uint32_t*)&h3);
            *(uint4*)(g_x0h + (size_t)n * 32 + (c8 >> 1)) = p;
        }
    }
}

// Pull-mode conv: node per 16-lane group; gather fp16 x[src] * w_rel[etype],
// mean + bias + tanh fused. layer=1: read g_x0h, write g_x1h mirror.
// layer=2: read g_x1h, write g_x0 fp32.
__global__ void conv_kernel(const float* __restrict__ b, int layer) {
    __shared__ __align__(16) float ws[R_REL * DIM];  // 16 KB
    for (int i = threadIdx.x; i < R_REL * DIM; i += blockDim.x) ws[i] = g_wrel[i];
    __syncthreads();

    const __half2* __restrict__ xh = (layer == 1) ? g_x0h : g_x1h;
    int group = threadIdx.x >> 4;
    int lane  = threadIdx.x & 15;
    int n = blockIdx.x * 16 + group;   // grid covers exactly N_NODES

    int start = __ldg(&g_rowptr[n]);
    int end   = __ldg(&g_rowptr[n + 1]);

    float4 acc = make_float4(0.f, 0.f, 0.f, 0.f);
    int i = start;
    for (; i + 2 <= end; i += 2) {
        unsigned pk0 = __ldg(&g_eadj[i]);
        unsigned pk1 = __ldg(&g_eadj[i + 1]);
        uint2 p0 = *(const uint2*)(xh + (size_t)(pk0 >> 6) * 32 + lane * 2);
        uint2 p1 = *(const uint2*)(xh + (size_t)(pk1 >> 6) * 32 + lane * 2);
        float4 w0 = *(const float4*)&ws[(pk0 & 63) * DIM + lane * 4];
        float4 w1 = *(const float4*)&ws[(pk1 & 63) * DIM + lane * 4];
        float2 a0 = __half22float2(*(__half2*)&p0.x);
        float2 a1 = __half22float2(*(__half2*)&p0.y);
        float2 c0 = __half22float2(*(__half2*)&p1.x);
        float2 c1 = __half22float2(*(__half2*)&p1.y);
        acc.x += a0.x * w0.x; acc.y += a0.y * w0.y;
        acc.z += a1.x * w0.z; acc.w += a1.y * w0.w;
        acc.x += c0.x * w1.x; acc.y += c0.y * w1.y;
        acc.z += c1.x * w1.z; acc.w += c1.y * w1.w;
    }
    if (i < end) {
        unsigned pk = __ldg(&g_eadj[i]);
        uint2 p = *(const uint2*)(xh + (size_t)(pk >> 6) * 32 + lane * 2);
        float4 wv = *(const float4*)&ws[(pk & 63) * DIM + lane * 4];
        float2 f0 = __half22float2(*(__half2*)&p.x);
        float2 f1 = __half22float2(*(__half2*)&p.y);
        acc.x += f0.x * wv.x; acc.y += f0.y * wv.y;
        acc.z += f1.x * wv.z; acc.w += f1.y * wv.w;
    }

    int deg = end - start;
    float inv = 1.0f / (float)(deg > 0 ? deg : 1);
    float4 bb = *(const float4*)(b + lane * 4);
    float4 v;
    v.x = tanhf(acc.x * inv + bb.x);
    v.y = tanhf(acc.y * inv + bb.y);
    v.z = tanhf(acc.z * inv + bb.z);
    v.w = tanhf(acc.w * inv + bb.w);

    if (layer == 1) {
        __half2 h0 = __floats2half2_rn(v.x, v.y);
        __half2 h1 = __floats2half2_rn(v.z, v.w);
        uint2 p = make_uint2(*(uint32_t*)&h0, *(uint32_t*)&h1);
        *(uint2*)(g_x1h + (size_t)n * 32 + lane * 2) = p;
    } else {
        *(float4*)&g_x0[(size_t)n * DIM + lane * 4] = v;
    }
}

// out = x2 @ fc2_w + fc2_b   (x2 in g_x0).  16 nodes per block.
__global__ void out_kernel(const float* __restrict__ fc2w,
                           const float* __restrict__ fc2b,
                           float* __restrict__ out) {
    __shared__ float ws[DIM * NCLS];  // 4 KB
    __shared__ float xs[16 * DIM];    // 4 KB
    int tid = threadIdx.x;
    for (int i = tid; i < DIM * NCLS; i += 256) ws[i] = fc2w[i];
    int base = blockIdx.x * 16;
    for (int i = tid; i < 16 * DIM; i += 256) xs[i] = g_x0[(size_t)base * DIM + i];
    __syncthreads();
    int nl = tid >> 4, k = tid & 15;
    float acc = fc2b[k];
    #pragma unroll
    for (int c = 0; c < DIM; ++c)
        acc += xs[nl * DIM + c] * ws[c * NCLS + k];
    out[(size_t)(base + nl) * NCLS + k] = acc;
}

// ---------------- launch ----------------
extern "C" void kernel_launch(void* const* d_in, const int* in_sizes, int n_in,
                              void* d_out, int out_size) {
    const float* x_in   = (const float*)d_in[0];
    const float* rel_x  = (const float*)d_in[1];
    const int*   ei     = (const int*)  d_in[2];
    const int*   et     = (const int*)  d_in[3];
    const int*   rel_ei = (const int*)  d_in[4];
    const float* rel_ea = (const float*)d_in[5];
    const float* fc1    = (const float*)d_in[6];
    const float* W_nn   = (const float*)d_in[7];
    const float* b_nn   = (const float*)d_in[8];
    const float* b1     = (const float*)d_in[9];
    const float* b2     = (const float*)d_in[10];
    const float* fc2w   = (const float*)d_in[11];
    const float* fc2b   = (const float*)d_in[12];
    float* out = (float*)d_out;

    // CSR build (reused by both conv sweeps)
    zero_cnt_kernel<<<(N_NODES + 255) / 256, 256>>>();
    count_kernel<<<(N_EDGES + 255) / 256, 256>>>(ei + N_EDGES);
    scan_kernel<<<1, 1024>>>();
    fill_kernel<<<(N_EDGES + 255) / 256, 256>>>(ei, et);

    rel_kernel<<<1, 1024>>>(rel_x, rel_ei, rel_ea, W_nn, b_nn);
    proj_kernel<<<(N_NODES + 127) / 128, 256>>>(x_in, fc1);

    conv_kernel<<<N_NODES / 16, 256>>>(b1, 1);   // x1 (fp16 mirror)
    conv_kernel<<<N_NODES / 16, 256>>>(b2, 2);   // x2 (fp32 into g_x0)

    out_kernel<<<N_NODES / 16, 256>>>(fc2w, fc2b, out);
}